// round 9
// baseline (speedup 1.0000x reference)
#include <cuda_runtime.h>
#include <stdint.h>

#define N1 8192
#define N2 8192
#define D  1024
#define C  128
#define NTY 8

// packed dual-fp32 FMA: d.lo += a.lo*b.lo, d.hi += a.hi*b.hi (SASS FFMA2, 2x fp32 tput)
#define FMA_F32X2(d, a, b) \
    asm("fma.rn.f32x2 %0, %1, %2, %0;" : "+l"(d) : "l"(a), "l"(b))

// ---------------- device scratch (static: no runtime allocation) ----------------
__device__ float g_sl1[N1 * C];          // gathered slot slices of ft_1  (4 MB)
__device__ float g_sl2[N2 * C];          // gathered slot slices of ft_2  (4 MB)
__device__ int   g_perm1[N1];
__device__ int   g_perm2[N2];
__device__ int   g_start1[NTY], g_cnt1[NTY];
__device__ int   g_start2[NTY], g_cnt2[NTY];
__device__ int   g_tilePrefix[NTY + 1];
__device__ int   g_totalTiles;
__device__ int   g_is64;                 // 1 if type arrays are int64, 0 if int32

// ---------------- dtype detection --------------------------------------------
__global__ void detect_kernel(const int* __restrict__ tyraw) {
    __shared__ int sAny;
    if (threadIdx.x == 0) sAny = 0;
    __syncthreads();
    int any = 0;
    for (int i = threadIdx.x; i < 4096; i += blockDim.x)
        any |= (tyraw[2 * i + 1] != 0);
    if (any) atomicOr(&sAny, 1);
    __syncthreads();
    if (threadIdx.x == 0) g_is64 = sAny ? 0 : 1;
}

__device__ __forceinline__ int load_type(const void* ty, int i, int is64) {
    int t = is64 ? (int)((const long long*)ty)[i] : ((const int*)ty)[i];
    return t & 7;
}

// ---------------- counting sort (stable compaction per type bin) ----------------
__global__ void compact_kernel(const void* __restrict__ ty1,
                               const void* __restrict__ ty2) {
    __shared__ int sTy[N1];
    __shared__ int sBase;
    const int which = blockIdx.x >> 3;
    const int t     = blockIdx.x & 7;
    const void* ty = which ? ty2 : ty1;
    int* perm      = which ? g_perm2 : g_perm1;
    const int n = which ? N2 : N1;
    const int tid = threadIdx.x;
    const int is64 = g_is64;

    if (tid == 0) sBase = 0;
    __syncthreads();
    for (int i = tid; i < n; i += blockDim.x) sTy[i] = load_type(ty, i, is64);
    __syncthreads();

    int lc = 0;
    for (int i = tid; i < n; i += blockDim.x) lc += (sTy[i] < t) ? 1 : 0;
#pragma unroll
    for (int o = 16; o > 0; o >>= 1) lc += __shfl_down_sync(0xffffffffu, lc, o);
    if ((tid & 31) == 0) atomicAdd(&sBase, lc);
    __syncthreads();

    if (tid < 32) {
        int off = sBase;
        for (int base = 0; base < n; base += 32) {
            int i = base + tid;
            int e = (sTy[i] == t) ? 1 : 0;
            unsigned m = __ballot_sync(0xffffffffu, e != 0);
            if (e) perm[off + __popc(m & ((1u << tid) - 1u))] = i;
            off += __popc(m);
        }
        if (tid == 0) {
            if (which) { g_start2[t] = sBase; g_cnt2[t] = off - sBase; }
            else       { g_start1[t] = sBase; g_cnt1[t] = off - sBase; }
        }
    }
}

// ---------------- tile plan ----------------------------------------------------
__global__ void plan_kernel() {
    int tp = 0;
    for (int t = 0; t < NTY; t++) {
        g_tilePrefix[t] = tp;
        int gm = (g_cnt1[t] + 127) >> 7;
        int gn = (g_cnt2[t] + 127) >> 7;
        tp += gm * gn;
    }
    g_tilePrefix[NTY] = tp;
    g_totalTiles = tp;
}

// ---------------- gather slot slices --------------------------------------------
__global__ void gather_kernel(const float* __restrict__ ft1,
                              const float* __restrict__ ft2,
                              const void* __restrict__ ty1,
                              const void* __restrict__ ty2) {
    int gw   = (blockIdx.x * blockDim.x + threadIdx.x) >> 5;
    int lane = threadIdx.x & 31;
    const int is64 = g_is64;
    const float* ft;
    const void* ty;
    float* dst;
    int r;
    if (gw < N1) { ft = ft1; ty = ty1; dst = g_sl1; r = gw; }
    else         { ft = ft2; ty = ty2; dst = g_sl2; r = gw - N1; }
    int t = load_type(ty, r, is64);
    const float4* src = (const float4*)(ft + (size_t)r * D + (size_t)t * C);
    float4* d = (float4*)(dst + (size_t)r * C);
    d[lane] = src[lane];
}

// ---- helpers for the FFMA2 mainloop --------------------------------------------
// stage 4 k-values of A duplicated: As_dup[k][2*row] = As_dup[k][2*row+1] = val
__device__ __forceinline__ void stage_a_dup(float (*A)[256], int lcol, int lrow, float4 v) {
    float2 d;
    d.x = d.y = v.x; *(float2*)&A[lcol + 0][2 * lrow] = d;
    d.x = d.y = v.y; *(float2*)&A[lcol + 1][2 * lrow] = d;
    d.x = d.y = v.z; *(float2*)&A[lcol + 2][2 * lrow] = d;
    d.x = d.y = v.w; *(float2*)&A[lcol + 3][2 * lrow] = d;
}
__device__ __forceinline__ void stage_b(float (*B)[128], int lcol, int lrow, float4 v) {
    B[lcol + 0][lrow] = v.x;
    B[lcol + 1][lrow] = v.y;
    B[lcol + 2][lrow] = v.z;
    B[lcol + 3][lrow] = v.w;
}

// 8 k-steps of the 8x8 microtile via FFMA2 (acc pairs over columns)
__device__ __forceinline__ void mma8(unsigned long long acc2[8][4],
                                     float (*As_c)[256], float (*Bs_c)[128],
                                     int row0, int col0) {
#pragma unroll
    for (int k = 0; k < 8; k++) {
        ulonglong2 A0 = *(const ulonglong2*)&As_c[k][2 * row0];
        ulonglong2 A1 = *(const ulonglong2*)&As_c[k][2 * row0 + 4];
        ulonglong2 A2 = *(const ulonglong2*)&As_c[k][2 * row0 + 8];
        ulonglong2 A3 = *(const ulonglong2*)&As_c[k][2 * row0 + 12];
        ulonglong2 B0 = *(const ulonglong2*)&Bs_c[k][col0];
        ulonglong2 B1 = *(const ulonglong2*)&Bs_c[k][col0 + 4];

        FMA_F32X2(acc2[0][0], A0.x, B0.x); FMA_F32X2(acc2[0][1], A0.x, B0.y);
        FMA_F32X2(acc2[0][2], A0.x, B1.x); FMA_F32X2(acc2[0][3], A0.x, B1.y);
        FMA_F32X2(acc2[1][0], A0.y, B0.x); FMA_F32X2(acc2[1][1], A0.y, B0.y);
        FMA_F32X2(acc2[1][2], A0.y, B1.x); FMA_F32X2(acc2[1][3], A0.y, B1.y);
        FMA_F32X2(acc2[2][0], A1.x, B0.x); FMA_F32X2(acc2[2][1], A1.x, B0.y);
        FMA_F32X2(acc2[2][2], A1.x, B1.x); FMA_F32X2(acc2[2][3], A1.x, B1.y);
        FMA_F32X2(acc2[3][0], A1.y, B0.x); FMA_F32X2(acc2[3][1], A1.y, B0.y);
        FMA_F32X2(acc2[3][2], A1.y, B1.x); FMA_F32X2(acc2[3][3], A1.y, B1.y);
        FMA_F32X2(acc2[4][0], A2.x, B0.x); FMA_F32X2(acc2[4][1], A2.x, B0.y);
        FMA_F32X2(acc2[4][2], A2.x, B1.x); FMA_F32X2(acc2[4][3], A2.x, B1.y);
        FMA_F32X2(acc2[5][0], A2.y, B0.x); FMA_F32X2(acc2[5][1], A2.y, B0.y);
        FMA_F32X2(acc2[5][2], A2.y, B1.x); FMA_F32X2(acc2[5][3], A2.y, B1.y);
        FMA_F32X2(acc2[6][0], A3.x, B0.x); FMA_F32X2(acc2[6][1], A3.x, B0.y);
        FMA_F32X2(acc2[6][2], A3.x, B1.x); FMA_F32X2(acc2[6][3], A3.x, B1.y);
        FMA_F32X2(acc2[7][0], A3.y, B0.x); FMA_F32X2(acc2[7][1], A3.y, B0.y);
        FMA_F32X2(acc2[7][2], A3.y, B1.x); FMA_F32X2(acc2[7][3], A3.y, B1.y);
    }
}

__device__ __forceinline__ float lo32(unsigned long long v) {
    return __uint_as_float((unsigned)v);
}
__device__ __forceinline__ float hi32(unsigned long long v) {
    return __uint_as_float((unsigned)(v >> 32));
}

// ---------------- cross GEMM: out = sl1 @ sl2^T, K=128, all 8192x8192 ----------
// launch_bounds(256, 1): ~150-reg live set MUST NOT be capped at 128 (R8 spilled)
__global__ __launch_bounds__(256, 1)
void cross_gemm(float* __restrict__ out) {
    __shared__ __align__(16) float As[2][8][256];   // duplicated A values
    __shared__ __align__(16) float Bs[2][8][128];
    const int tid  = threadIdx.x;
    const int bi   = blockIdx.y, bj = blockIdx.x;
    const int lrow = tid >> 1;
    const int lcol = (tid & 1) << 2;
    const float* Ag = g_sl1 + (size_t)(bi * 128 + lrow) * C + lcol;
    const float* Bg = g_sl2 + (size_t)(bj * 128 + lrow) * C + lcol;
    const int row0 = (tid >> 4) << 3;
    const int col0 = (tid & 15) << 3;

    unsigned long long acc2[8][4];
#pragma unroll
    for (int i = 0; i < 8; i++)
#pragma unroll
        for (int jp = 0; jp < 4; jp++) acc2[i][jp] = 0ULL;

    stage_a_dup(As[0], lcol, lrow, *(const float4*)Ag);
    stage_b(Bs[0], lcol, lrow, *(const float4*)Bg);
    __syncthreads();

    float (*As_c)[256] = As[0], (*As_n)[256] = As[1];
    float (*Bs_c)[128] = Bs[0], (*Bs_n)[128] = Bs[1];

#pragma unroll 1
    for (int kt = 0; kt < 16; kt++) {
        float4 na, nb;
        const bool pf = (kt < 15);
        if (pf) {
            na = *(const float4*)(Ag + (kt + 1) * 8);
            nb = *(const float4*)(Bg + (kt + 1) * 8);
        }
        mma8(acc2, As_c, Bs_c, row0, col0);
        if (pf) {
            stage_a_dup(As_n, lcol, lrow, na);
            stage_b(Bs_n, lcol, lrow, nb);
            __syncthreads();
            float (*tA)[256] = As_c; As_c = As_n; As_n = tA;
            float (*tB)[128] = Bs_c; Bs_c = Bs_n; Bs_n = tB;
        }
    }

    float* obase = out + (size_t)(bi * 128 + row0) * N2 + (size_t)(bj * 128 + col0);
#pragma unroll
    for (int i = 0; i < 8; i++) {
        *(float4*)(obase + (size_t)i * N2) =
            make_float4(lo32(acc2[i][0]), hi32(acc2[i][0]), lo32(acc2[i][1]), hi32(acc2[i][1]));
        *(float4*)(obase + (size_t)i * N2 + 4) =
            make_float4(lo32(acc2[i][2]), hi32(acc2[i][2]), lo32(acc2[i][3]), hi32(acc2[i][3]));
    }
}

// ---------------- same-type block GEMM: full K=1024, overwrite same pairs ------
__global__ __launch_bounds__(256, 1)
void same_gemm(const float* __restrict__ ft1, const float* __restrict__ ft2,
               float* __restrict__ out) {
    __shared__ __align__(16) float As[2][8][256];   // duplicated A values
    __shared__ __align__(16) float Bs[2][8][128];
    __shared__ int sRowG[128];
    __shared__ int sColG[128];
    const int tid = threadIdx.x;

    const int total = g_totalTiles;
    for (int tile = blockIdx.x; tile < total; tile += gridDim.x) {
        int t = 0;
        while (tile >= g_tilePrefix[t + 1]) t++;
        const int local = tile - g_tilePrefix[t];
        const int m = g_cnt1[t], n = g_cnt2[t];
        const int gn = (n + 127) >> 7;
        const int ti = local / gn, tj = local % gn;
        const int mbase = ti * 128, nbase = tj * 128;

        __syncthreads();  // protect sRowG/sColG reuse across grid-stride tiles
        if (tid < 128) {
            int ii = mbase + tid;
            sRowG[tid] = (ii < m) ? g_perm1[g_start1[t] + ii] : -1;
            int jj = nbase + tid;
            sColG[tid] = (jj < n) ? g_perm2[g_start2[t] + jj] : -1;
        }
        __syncthreads();

        const int lrow = tid >> 1;
        const int lcol = (tid & 1) << 2;
        const int ar = sRowG[lrow];
        const int br = sColG[lrow];
        const float* Ag = ft1 + (size_t)(ar < 0 ? 0 : ar) * D + lcol;
        const float* Bg = ft2 + (size_t)(br < 0 ? 0 : br) * D + lcol;
        const int row0 = (tid >> 4) << 3;
        const int col0 = (tid & 15) << 3;

        unsigned long long acc2[8][4];
#pragma unroll
        for (int i = 0; i < 8; i++)
#pragma unroll
            for (int jp = 0; jp < 4; jp++) acc2[i][jp] = 0ULL;

        stage_a_dup(As[0], lcol, lrow, *(const float4*)Ag);
        stage_b(Bs[0], lcol, lrow, *(const float4*)Bg);
        __syncthreads();

        float (*As_c)[256] = As[0], (*As_n)[256] = As[1];
        float (*Bs_c)[128] = Bs[0], (*Bs_n)[128] = Bs[1];

#pragma unroll 1
        for (int kt = 0; kt < 128; kt++) {
            float4 na, nb;
            const bool pf = (kt < 127);
            if (pf) {
                na = *(const float4*)(Ag + (kt + 1) * 8);
                nb = *(const float4*)(Bg + (kt + 1) * 8);
            }
            mma8(acc2, As_c, Bs_c, row0, col0);
            if (pf) {
                stage_a_dup(As_n, lcol, lrow, na);
                stage_b(Bs_n, lcol, lrow, nb);
                __syncthreads();
                float (*tA)[256] = As_c; As_c = As_n; As_n = tA;
                float (*tB)[128] = Bs_c; Bs_c = Bs_n; Bs_n = tB;
            }
        }

        // scattered epilogue
        int cols[8];
#pragma unroll
        for (int j = 0; j < 8; j++) cols[j] = sColG[col0 + j];
#pragma unroll
        for (int i = 0; i < 8; i++) {
            int r = sRowG[row0 + i];
            if (r >= 0) {
                float* orow = out + (size_t)r * N2;
                float v[8];
#pragma unroll
                for (int jp = 0; jp < 4; jp++) {
                    v[2 * jp]     = lo32(acc2[i][jp]);
                    v[2 * jp + 1] = hi32(acc2[i][jp]);
                }
#pragma unroll
                for (int j = 0; j < 8; j++)
                    if (cols[j] >= 0) orow[cols[j]] = v[j];
            }
        }
    }
}

// -------------------------------- launch ---------------------------------------
extern "C" void kernel_launch(void* const* d_in, const int* in_sizes, int n_in,
                              void* d_out, int out_size) {
    const float* ft1 = (const float*)d_in[0];
    const float* ft2 = (const float*)d_in[1];
    const void*  ty1 = d_in[2];
    const void*  ty2 = d_in[3];
    float* out = (float*)d_out;

    detect_kernel<<<1, 256>>>((const int*)ty1);
    compact_kernel<<<16, 256>>>(ty1, ty2);
    plan_kernel<<<1, 1>>>();
    gather_kernel<<<(N1 + N2) / 8, 256>>>(ft1, ft2, ty1, ty2);

    dim3 gc(N2 / 128, N1 / 128);
    cross_gemm<<<gc, 256>>>(out);             // writes every output element (cross)
    same_gemm<<<1024, 256>>>(ft1, ft2, out);  // overwrites same-type pairs (full)
}

// round 11
// speedup vs baseline: 2.4038x; 2.4038x over previous
#include <cuda_runtime.h>
#include <cuda_bf16.h>
#include <stdint.h>

#define N1 8192
#define N2 8192
#define D  1024
#define C  128
#define NTY 8
#define KE3 3072            // 3*D  expanded K (same-type GEMM)
#define KC3 384             // 3*C  expanded K (cross GEMM)

#define STAGES      3
#define CHUNK_K     64                       // bf16 k per chunk
#define STAGE_HALF  (128 * 128)              // 128 rows x 128B  = 16 KB
#define STAGE_BYTES (2 * STAGE_HALF)         // A + B            = 32 KB
#define SMEM_BYTES  (STAGES * STAGE_BYTES)   // 96 KB

// ---------------- device scratch (static: no runtime allocation) ----------------
__device__ __align__(1024) __nv_bfloat16 g_ft1p[(size_t)N1 * KE3];  // perm order, (hi,hi,lo)
__device__ __align__(1024) __nv_bfloat16 g_ft2p[(size_t)N2 * KE3];  // perm order, (hi,lo,hi)
__device__ __align__(1024) __nv_bfloat16 g_sl1x[(size_t)N1 * KC3];  // orig order, (hi,hi,lo)
__device__ __align__(1024) __nv_bfloat16 g_sl2x[(size_t)N2 * KC3];  // orig order, (hi,lo,hi)
__device__ int g_perm1[N1], g_perm2[N2];
__device__ int g_start1[NTY], g_cnt1[NTY];
__device__ int g_start2[NTY], g_cnt2[NTY];
__device__ int g_tilePrefix[NTY + 1];
__device__ int g_totalTiles;
__device__ int g_is64;

// ---------------- small PTX helpers (all base-ISA, compute_103-safe) ------------
__device__ __forceinline__ uint32_t smem_u32(const void* p) {
    uint32_t a;
    asm("{ .reg .u64 t; cvta.to.shared.u64 t, %1; cvt.u32.u64 %0, t; }" : "=r"(a) : "l"(p));
    return a;
}
__device__ __forceinline__ void cp16(uint32_t s, const void* g) {
    asm volatile("cp.async.cg.shared.global [%0], [%1], 16;" :: "r"(s), "l"(g));
}
#define CP_COMMIT() asm volatile("cp.async.commit_group;" ::: "memory")
#define CP_WAIT1()  asm volatile("cp.async.wait_group 1;" ::: "memory")

__device__ __forceinline__ void ldsm4(uint32_t r[4], uint32_t addr) {
    asm volatile("ldmatrix.sync.aligned.m8n8.x4.shared.b16 {%0,%1,%2,%3}, [%4];"
                 : "=r"(r[0]), "=r"(r[1]), "=r"(r[2]), "=r"(r[3]) : "r"(addr));
}
__device__ __forceinline__ void mma16816(float c[4], const uint32_t a[4],
                                         uint32_t b0, uint32_t b1) {
    asm volatile("mma.sync.aligned.m16n8k16.row.col.f32.bf16.bf16.f32 "
                 "{%0,%1,%2,%3}, {%4,%5,%6,%7}, {%8,%9}, {%0,%1,%2,%3};"
                 : "+f"(c[0]), "+f"(c[1]), "+f"(c[2]), "+f"(c[3])
                 : "r"(a[0]), "r"(a[1]), "r"(a[2]), "r"(a[3]), "r"(b0), "r"(b1));
}
// swizzled smem address: rows 128B, 16B quads, quad' = quad ^ (row & 7)
__device__ __forceinline__ uint32_t swz(uint32_t base, int row, int quad) {
    return base + row * 128 + ((quad ^ (row & 7)) << 4);
}

// ---------------- dtype detection (int64 vs silently-downgraded int32) ----------
__global__ void detect_kernel(const int* __restrict__ tyraw) {
    __shared__ int sAny;
    if (threadIdx.x == 0) sAny = 0;
    __syncthreads();
    int any = 0;
    for (int i = threadIdx.x; i < 4096; i += blockDim.x) any |= (tyraw[2 * i + 1] != 0);
    if (any) atomicOr(&sAny, 1);
    __syncthreads();
    if (threadIdx.x == 0) g_is64 = sAny ? 0 : 1;
}
__device__ __forceinline__ int load_type(const void* ty, int i, int is64) {
    int t = is64 ? (int)((const long long*)ty)[i] : ((const int*)ty)[i];
    return t & 7;
}

// ---------------- counting sort (stable compaction per type bin) ----------------
__global__ void compact_kernel(const void* __restrict__ ty1, const void* __restrict__ ty2) {
    __shared__ int sTy[N1];
    __shared__ int sBase;
    const int which = blockIdx.x >> 3;
    const int t     = blockIdx.x & 7;
    const void* ty = which ? ty2 : ty1;
    int* perm      = which ? g_perm2 : g_perm1;
    const int n = which ? N2 : N1;
    const int tid = threadIdx.x;
    const int is64 = g_is64;

    if (tid == 0) sBase = 0;
    __syncthreads();
    for (int i = tid; i < n; i += blockDim.x) sTy[i] = load_type(ty, i, is64);
    __syncthreads();
    int lc = 0;
    for (int i = tid; i < n; i += blockDim.x) lc += (sTy[i] < t) ? 1 : 0;
#pragma unroll
    for (int o = 16; o > 0; o >>= 1) lc += __shfl_down_sync(0xffffffffu, lc, o);
    if ((tid & 31) == 0) atomicAdd(&sBase, lc);
    __syncthreads();
    if (tid < 32) {
        int off = sBase;
        for (int base = 0; base < n; base += 32) {
            int i = base + tid;
            int e = (sTy[i] == t) ? 1 : 0;
            unsigned m = __ballot_sync(0xffffffffu, e != 0);
            if (e) perm[off + __popc(m & ((1u << tid) - 1u))] = i;
            off += __popc(m);
        }
        if (tid == 0) {
            if (which) { g_start2[t] = sBase; g_cnt2[t] = off - sBase; }
            else       { g_start1[t] = sBase; g_cnt1[t] = off - sBase; }
        }
    }
}

__global__ void plan_kernel() {
    int tp = 0;
    for (int t = 0; t < NTY; t++) {
        g_tilePrefix[t] = tp;
        tp += ((g_cnt1[t] + 127) >> 7) * ((g_cnt2[t] + 127) >> 7);
    }
    g_tilePrefix[NTY] = tp;
    g_totalTiles = tp;
}

// ---------------- convert: fp32 -> bf16 hi/lo expanded operands -----------------
// one block per (which, pos); per original k: A side (hi,hi,lo), B side (hi,lo,hi)
__global__ void convert_kernel(const float* __restrict__ ft1, const float* __restrict__ ft2,
                               const void* __restrict__ ty1, const void* __restrict__ ty2) {
    const int pos   = blockIdx.x & (N1 - 1);
    const int which = blockIdx.x >> 13;
    const float* ft = which ? ft2 : ft1;
    const void* ty  = which ? ty2 : ty1;
    const int* perm = which ? g_perm2 : g_perm1;
    __nv_bfloat16* ftp = which ? g_ft2p : g_ft1p;
    __nv_bfloat16* slx = which ? g_sl2x : g_sl1x;
    const int tid  = threadIdx.x;                // 128 threads x 8 k each
    const int orig = perm[pos];
    const int t    = load_type(ty, orig, g_is64);

    const float4* s = (const float4*)(ft + (size_t)orig * D) + tid * 2;
    float4 a = s[0], b = s[1];
    float x[8] = {a.x, a.y, a.z, a.w, b.x, b.y, b.z, b.w};

    unsigned hi[8], lo[8];
#pragma unroll
    for (int i = 0; i < 8; i++) {
        __nv_bfloat16 h = __float2bfloat16(x[i]);
        __nv_bfloat16 l = __float2bfloat16(x[i] - __bfloat162float(h));
        hi[i] = __bfloat16_as_ushort(h);
        lo[i] = __bfloat16_as_ushort(l);
    }

    unsigned u[12];
#pragma unroll
    for (int p = 0; p < 4; p++) {
        unsigned he = hi[2 * p], ho = hi[2 * p + 1], le = lo[2 * p], lu = lo[2 * p + 1];
        if (which == 0) {   // (hi,hi,lo) per k
            u[3 * p + 0] = he | (he << 16);
            u[3 * p + 1] = le | (ho << 16);
            u[3 * p + 2] = ho | (lu << 16);
        } else {            // (hi,lo,hi) per k
            u[3 * p + 0] = he | (le << 16);
            u[3 * p + 1] = he | (ho << 16);
            u[3 * p + 2] = lu | (ho << 16);
        }
    }
    uint4 w0 = make_uint4(u[0], u[1], u[2], u[3]);
    uint4 w1 = make_uint4(u[4], u[5], u[6], u[7]);
    uint4 w2 = make_uint4(u[8], u[9], u[10], u[11]);

    uint4* df = (uint4*)((char*)ftp + (size_t)pos * (KE3 * 2) + tid * 48);
    df[0] = w0; df[1] = w1; df[2] = w2;

    if (tid >= t * 16 && tid < t * 16 + 16) {
        uint4* ds = (uint4*)((char*)slx + (size_t)orig * (KC3 * 2) + (tid - t * 16) * 48);
        ds[0] = w0; ds[1] = w1; ds[2] = w2;
    }
}

// ---------------- GEMM building blocks -------------------------------------------
// load one 128x64-bf16 chunk of A and B into a swizzled smem stage
__device__ __forceinline__ void issue_chunk(uint32_t stA, uint32_t stB,
        const char* gA, const char* gB, long strA, long strB,
        long rowA0, long rowB0, long maxA, long maxB, int kOff, int tid) {
    int row = tid >> 1;
    int q0  = (tid & 1) << 2;
    long ra = rowA0 + row; if (ra > maxA) ra = maxA;
    long rb = rowB0 + row; if (rb > maxB) rb = maxB;
    const char* pa = gA + ra * strA + kOff;
    const char* pb = gB + rb * strB + kOff;
#pragma unroll
    for (int i = 0; i < 4; i++) {
        int q = q0 + i;
        cp16(swz(stA, row, q), pa + q * 16);
        cp16(swz(stB, row, q), pb + q * 16);
    }
}

// one 128x128x64 chunk of MMAs for this warp (warp tile 64x32)
__device__ __forceinline__ void mma_chunk(float acc[4][4][4], uint32_t stA, uint32_t stB,
                                          int wm, int wn, int lane) {
#pragma unroll
    for (int j = 0; j < 4; j++) {            // k16 steps within chunk
        uint32_t a[4][4];
#pragma unroll
        for (int mi = 0; mi < 4; mi++) {
            int row  = wm * 64 + mi * 16 + (lane & 15);
            int quad = 2 * j + (lane >> 4);
            ldsm4(a[mi], swz(stA, row, quad));
        }
        uint32_t b[2][4];
#pragma unroll
        for (int np = 0; np < 2; np++) {
            int row  = wn * 32 + np * 16 + (lane & 7) + ((lane & 16) >> 1);
            int quad = 2 * j + ((lane >> 3) & 1);
            ldsm4(b[np], swz(stB, row, quad));
        }
#pragma unroll
        for (int mi = 0; mi < 4; mi++)
#pragma unroll
            for (int ni = 0; ni < 4; ni++)
                mma16816(acc[mi][ni], a[mi], b[ni >> 1][(ni & 1) * 2],
                         b[ni >> 1][(ni & 1) * 2 + 1]);
    }
}

// ---------------- cross GEMM: out = sl1x @ sl2x^T (all pairs), K=384 -------------
__global__ __launch_bounds__(256)
void cross_mma(float* __restrict__ out) {
    extern __shared__ char smc[];
    uint32_t sb = smem_u32(smc);
    const int tid = threadIdx.x, lane = tid & 31, warp = tid >> 5;
    const int wm = warp & 1, wn = warp >> 1;
    const int bi = blockIdx.y, bj = blockIdx.x;
    const char* gA = (const char*)g_sl1x;
    const char* gB = (const char*)g_sl2x;
    const long strA = KC3 * 2, strB = KC3 * 2;
    const long rA0 = (long)bi * 128, rB0 = (long)bj * 128;
    const int NC = KC3 / CHUNK_K;   // 6

    float acc[4][4][4];
#pragma unroll
    for (int mi = 0; mi < 4; mi++)
#pragma unroll
        for (int ni = 0; ni < 4; ni++)
#pragma unroll
            for (int q = 0; q < 4; q++) acc[mi][ni][q] = 0.f;

    issue_chunk(sb, sb + STAGE_HALF, gA, gB, strA, strB, rA0, rB0, N1 - 1, N2 - 1, 0, tid);
    CP_COMMIT();
    issue_chunk(sb + STAGE_BYTES, sb + STAGE_BYTES + STAGE_HALF, gA, gB, strA, strB,
                rA0, rB0, N1 - 1, N2 - 1, 128, tid);
    CP_COMMIT();

#pragma unroll 1
    for (int c = 0; c < NC; c++) {
        CP_WAIT1();
        __syncthreads();
        int cn = c + 2;
        if (cn < NC) {
            int s = cn % STAGES;
            issue_chunk(sb + s * STAGE_BYTES, sb + s * STAGE_BYTES + STAGE_HALF,
                        gA, gB, strA, strB, rA0, rB0, N1 - 1, N2 - 1, cn * 128, tid);
        }
        CP_COMMIT();
        int s = c % STAGES;
        mma_chunk(acc, sb + s * STAGE_BYTES, sb + s * STAGE_BYTES + STAGE_HALF, wm, wn, lane);
    }

    const int rbase = bi * 128 + wm * 64;
    const int cbase = bj * 128 + wn * 32;
#pragma unroll
    for (int mi = 0; mi < 4; mi++)
#pragma unroll
        for (int ni = 0; ni < 4; ni++) {
            int rr = rbase + mi * 16 + (lane >> 2);
            int cc = cbase + ni * 8 + ((lane & 3) << 1);
            *(float2*)(out + (size_t)rr * N2 + cc) =
                make_float2(acc[mi][ni][0], acc[mi][ni][1]);
            *(float2*)(out + (size_t)(rr + 8) * N2 + cc) =
                make_float2(acc[mi][ni][2], acc[mi][ni][3]);
        }
}

// ---------------- same-type GEMM: full K=3072, permuted rows, scatter ------------
__global__ __launch_bounds__(256)
void same_mma(float* __restrict__ out) {
    extern __shared__ char sms[];
    uint32_t sb = smem_u32(sms);
    const int tid = threadIdx.x, lane = tid & 31, warp = tid >> 5;
    const int wm = warp & 1, wn = warp >> 1;
    const char* gA = (const char*)g_ft1p;
    const char* gB = (const char*)g_ft2p;
    const long strA = KE3 * 2, strB = KE3 * 2;
    const int NC = KE3 / CHUNK_K;   // 48
    const int total = g_totalTiles;

#pragma unroll 1
    for (int tile = blockIdx.x; tile < total; tile += gridDim.x) {
        int t = 0;
        while (tile >= g_tilePrefix[t + 1]) t++;
        const int local = tile - g_tilePrefix[t];
        const int m = g_cnt1[t], n = g_cnt2[t];
        const int gn = (n + 127) >> 7;
        const int mbase = (local / gn) * 128, nbase = (local % gn) * 128;
        const int s1 = g_start1[t], s2 = g_start2[t];
        const long rA0 = s1 + mbase, rB0 = s2 + nbase;

        float acc[4][4][4];
#pragma unroll
        for (int mi = 0; mi < 4; mi++)
#pragma unroll
            for (int ni = 0; ni < 4; ni++)
#pragma unroll
                for (int q = 0; q < 4; q++) acc[mi][ni][q] = 0.f;

        issue_chunk(sb, sb + STAGE_HALF, gA, gB, strA, strB, rA0, rB0, N1 - 1, N2 - 1, 0, tid);
        CP_COMMIT();
        issue_chunk(sb + STAGE_BYTES, sb + STAGE_BYTES + STAGE_HALF, gA, gB, strA, strB,
                    rA0, rB0, N1 - 1, N2 - 1, 128, tid);
        CP_COMMIT();

#pragma unroll 1
        for (int c = 0; c < NC; c++) {
            CP_WAIT1();
            __syncthreads();
            int cn = c + 2;
            if (cn < NC) {
                int s = cn % STAGES;
                issue_chunk(sb + s * STAGE_BYTES, sb + s * STAGE_BYTES + STAGE_HALF,
                            gA, gB, strA, strB, rA0, rB0, N1 - 1, N2 - 1, cn * 128, tid);
            }
            CP_COMMIT();
            int s = c % STAGES;
            mma_chunk(acc, sb + s * STAGE_BYTES, sb + s * STAGE_BYTES + STAGE_HALF, wm, wn, lane);
        }

        // scattered epilogue via perm lookups (bounds-masked)
        int prow[8];
#pragma unroll
        for (int mi = 0; mi < 4; mi++) {
            int pm0 = mbase + wm * 64 + mi * 16 + (lane >> 2);
            prow[2 * mi]     = (pm0 < m)     ? g_perm1[s1 + pm0]     : -1;
            prow[2 * mi + 1] = (pm0 + 8 < m) ? g_perm1[s1 + pm0 + 8] : -1;
        }
        int pcol[8];
#pragma unroll
        for (int ni = 0; ni < 4; ni++) {
            int cn0 = nbase + wn * 32 + ni * 8 + ((lane & 3) << 1);
            pcol[2 * ni]     = (cn0 < n)     ? g_perm2[s2 + cn0]     : -1;
            pcol[2 * ni + 1] = (cn0 + 1 < n) ? g_perm2[s2 + cn0 + 1] : -1;
        }
#pragma unroll
        for (int mi = 0; mi < 4; mi++)
#pragma unroll
            for (int ni = 0; ni < 4; ni++) {
                int r0 = prow[2 * mi], r1 = prow[2 * mi + 1];
                if (r0 >= 0) {
                    float* o = out + (size_t)r0 * N2;
                    if (pcol[2 * ni] >= 0)     o[pcol[2 * ni]]     = acc[mi][ni][0];
                    if (pcol[2 * ni + 1] >= 0) o[pcol[2 * ni + 1]] = acc[mi][ni][1];
                }
                if (r1 >= 0) {
                    float* o = out + (size_t)r1 * N2;
                    if (pcol[2 * ni] >= 0)     o[pcol[2 * ni]]     = acc[mi][ni][2];
                    if (pcol[2 * ni + 1] >= 0) o[pcol[2 * ni + 1]] = acc[mi][ni][3];
                }
            }
        __syncthreads();   // smem stages reused by next tile's prologue
    }
}

// -------------------------------- launch ------------------------------------------
extern "C" void kernel_launch(void* const* d_in, const int* in_sizes, int n_in,
                              void* d_out, int out_size) {
    const float* ft1 = (const float*)d_in[0];
    const float* ft2 = (const float*)d_in[1];
    const void*  ty1 = d_in[2];
    const void*  ty2 = d_in[3];
    float* out = (float*)d_out;

    cudaFuncSetAttribute(cross_mma, cudaFuncAttributeMaxDynamicSharedMemorySize, SMEM_BYTES);
    cudaFuncSetAttribute(same_mma,  cudaFuncAttributeMaxDynamicSharedMemorySize, SMEM_BYTES);

    detect_kernel<<<1, 256>>>((const int*)ty1);
    compact_kernel<<<16, 256>>>(ty1, ty2);
    plan_kernel<<<1, 1>>>();
    convert_kernel<<<2 * N1, 128>>>(ft1, ft2, ty1, ty2);

    dim3 gc(64, 64);
    cross_mma<<<gc, 256, SMEM_BYTES>>>(out);       // writes every element (cross value)
    same_mma<<<1024, 256, SMEM_BYTES>>>(out);      // overwrites same-type pairs (full dot)
}